// round 9
// baseline (speedup 1.0000x reference)
#include <cuda_runtime.h>
#include <cuda_fp16.h>
#include <cstdint>

typedef unsigned int u32;

// ---------------- problem constants ----------------
#define Bn 8
#define Nn 40962
#define Dn 40
#define Hn 512
#define DDn 32
#define KTOT 160               // 4 neighbors * 40
#define M_TOT (Bn*Nn)          // 327696
#define TMm 64                 // rows per CTA (2 CTAs/SM)
#define NTH 256
#define NBLK ((M_TOT + TMm - 1)/TMm)   // 5121
#define KA16 10                // GEMM1 k-atoms of 16 (160/16)

// ---------------- smem layout (u32 indices) ----------------
// region A: max(Zf 5120 u32, red 6912 f32) = 6912
#define SM_Z    0
#define SM_B1   6912
#define SM_B2   (SM_B1 + 512)
#define SM_BAS  (SM_B2 + 32)
#define SM_U32S (SM_BAS + 256)         // 7712
#define SMEM_BYTES (SM_U32S*4)         // 30848

// ---------------- helpers ----------------
__device__ __forceinline__ u32 pack2(float a, float b) {
    __half2 h = __floats2half2_rn(a, b);
    return *(u32*)&h;
}
// paired gelu -> packed fp16x2, one MUFU per pair (tanh.approx.f16x2)
__device__ __forceinline__ u32 gelu2(float x0, float x1) {
    float u0 = x0 * (0.7978845608028654f + 0.0356774081f * x0 * x0);
    float u1 = x1 * (0.7978845608028654f + 0.0356774081f * x1 * x1);
    u32 uh = pack2(u0, u1);
    u32 th; asm("tanh.approx.f16x2 %0, %1;" : "=r"(th) : "r"(uh));
    __half2 t = *(__half2*)&th;
    __half2 xh = __floats2half2_rn(x0, x1);
    const __half2 c05 = __float2half2_rn(0.5f);
    __half2 h = __hmul2(xh, __hfma2(t, c05, c05));   // x * (0.5*t + 0.5)
    return *(u32*)&h;
}

// m16n8k16 fp16 HMMA: D(f32) += A(f16) * B(f16)
#define MMAH(D, A, b0, b1) \
    asm("mma.sync.aligned.m16n8k16.row.col.f32.f16.f16.f32 " \
        "{%0,%1,%2,%3}, {%4,%5,%6,%7}, {%8,%9}, {%0,%1,%2,%3};" \
        : "+f"((D)[0]), "+f"((D)[1]), "+f"((D)[2]), "+f"((D)[3]) \
        : "r"((A)[0]), "r"((A)[1]), "r"((A)[2]), "r"((A)[3]), "r"(b0), "r"(b1))

// ---------------- global scratch ----------------
// W1 fp16 B-fragments: [ka16(10)][npair(32)][lane(32)] x uint4
__device__ uint4 g_W1h[KA16 * 32 * 32];
// W2 fp16 B-fragments: [gka16(32)][pa(2)][lane(32)] x uint4
__device__ uint4 g_W2h[32 * 2 * 32];
__device__ float g_xbuf[(size_t)M_TOT * Dn];

// prep: W1 -> fp16 B-frag order.
// (ka, npair, lane, q): k = ka*16 + (lane%4)*2 + {0,1} + (q&1)*8
//                       n = npair*16 + (q>>1)*8 + lane/4
__global__ void prep_w1h(const float* __restrict__ W1) {
    int i = blockIdx.x * 256 + threadIdx.x;
    if (i >= KA16 * 32 * 32 * 4) return;
    int q    = i & 3;
    int lane = (i >> 2) & 31;
    int np   = (i >> 7) & 31;
    int ka   = i >> 12;
    int k = ka * 16 + (lane & 3) * 2 + (q & 1) * 8;
    int n = np * 16 + ((q >> 1) << 3) + (lane >> 2);
    float v0 = __ldg(&W1[(size_t)k * Hn + n]);
    float v1 = __ldg(&W1[(size_t)(k + 1) * Hn + n]);
    ((u32*)g_W1h)[i] = pack2(v0, v1);
}

// prep: W2 -> fp16 B-frag order (identity k mapping).
__global__ void prep_w2h(const float* __restrict__ W2) {
    int i = blockIdx.x * 256 + threadIdx.x;
    if (i >= 32 * 2 * 32 * 4) return;
    int q    = i & 3;
    int lane = (i >> 2) & 31;
    int pa   = (i >> 7) & 1;
    int gka  = i >> 8;
    int r = gka * 16 + (lane & 3) * 2 + (q & 1) * 8;
    int n = pa * 16 + ((q >> 1) << 3) + (lane >> 2);
    float v0 = __ldg(&W2[r * DDn + n]);
    float v1 = __ldg(&W2[(r + 1) * DDn + n]);
    ((u32*)g_W2h)[i] = pack2(v0, v1);
}

// ---------------- fused Euler step ----------------
__global__ void __launch_bounds__(NTH, 2)
step_kernel(const float* __restrict__ src, float* __restrict__ dst,
            const int* __restrict__ index,
            const uint4* __restrict__ W1h, const uint4* __restrict__ W2h,
            const float* __restrict__ b1, const float* __restrict__ b2)
{
    extern __shared__ u32 smu[];
    u32*   Zu  = smu;                    // fp16 A-frags: [mb(4)][ka16(10)][lane(32)][slot(4)]
    float* b1s = (float*)(smu + SM_B1);
    float* b2s = (float*)(smu + SM_B2);
    int*   bas = (int*)(smu + SM_BAS);
    float* red = (float*)smu;            // reduction scratch reuses Zf after GEMMs

    const int tid  = threadIdx.x;
    const int lane = tid & 31;
    const int wid  = tid >> 5;
    const int wm   = wid & 1;    // M warp: rows wm*32
    const int wn   = wid >> 1;   // N warp: 32-col slice within each 128-chunk (0..3)
    const int m0   = blockIdx.x * TMm;
    const int rows_valid = min(TMm, M_TOT - m0);

    // gather bases (one per thread: 64 rows x 4 neighbors)
    {
        int r = tid >> 2, k = tid & 3;
        int base = 0;
        if (r < rows_valid) {
            int m = m0 + r, b = m / Nn, n = m - b * Nn;
            base = (b * Nn + __ldg(&index[n * 4 + k])) * Dn;
        }
        bas[tid] = base;
    }
    if (tid < 128) ((float4*)b1s)[tid] = __ldg(((const float4*)b1) + tid);
    if (tid < 8)   ((float4*)b2s)[tid] = __ldg(((const float4*)b2) + tid);
    __syncthreads();

    // ---- gather Z -> fp16 A-fragment layout ----
    // d4-major mapping (adjacent lanes read adjacent 16B of the same row: ~5 L1
    // wavefronts per LDG.128 instead of 32) + full MLP batching (10 in flight).
    {
        float4 gv[10];
        int rka[10], d4a[10];
        #pragma unroll
        for (int j = 0; j < 10; ++j) {
            int t  = j * NTH + tid;          // 0..2559
            int rk = t / 10;
            int d4 = t - rk * 10;
            rka[j] = rk; d4a[j] = d4;
            gv[j] = __ldg((const float4*)(src + bas[rk] + d4 * 4));
        }
        #pragma unroll
        for (int j = 0; j < 10; ++j) {
            int rk = rka[j], d4 = d4a[j];
            int r  = rk >> 2, kn = rk & 3;
            int K  = kn * 40 + d4 * 4;
            int ka = K >> 4, kk = K & 15;
            int mb = r >> 4, rr = r & 15;
            int lane0 = ((rr & 7) << 2) + ((kk & 7) >> 1);
            int slot  = (rr >> 3) + ((kk >> 3) << 1);
            int base  = ((mb * KA16 + ka) * 32 + lane0) * 4 + slot;
            Zu[base]     = pack2(gv[j].x, gv[j].y);
            Zu[base + 4] = pack2(gv[j].z, gv[j].w);
        }
    }
    __syncthreads();

    float d2[2][4][4];
    #pragma unroll
    for (int m = 0; m < 2; ++m)
        #pragma unroll
        for (int a = 0; a < 4; ++a)
            #pragma unroll
            for (int q = 0; q < 4; ++q) d2[m][a][q] = 0.f;

    const uint4* Za = (const uint4*)Zu;
    const int np0  = wn * 2;     // warp's first npair within each 128-col chunk
    const int ccol = 2 * (lane & 3);

    // ---- 4 H-chunks of 128 cols, FULLY UNROLLED so ptxas can overlap the
    //      gelu/GEMM2 drain of chunk nc with GEMM1 loads/MMAs of chunk nc+1 ----
    #pragma unroll
    for (int nc = 0; nc < 4; ++nc) {
        const int npA = nc * 8 + np0;     // warp's npair indices: npA, npA+1
        float d1[2][4][4];
        #pragma unroll
        for (int m = 0; m < 2; ++m)
            #pragma unroll
            for (int a = 0; a < 4; ++a)
                #pragma unroll
                for (int q = 0; q < 4; ++q) d1[m][a][q] = 0.f;

        // distance-2 register prefetch of W1 fp16 B-frags (L2-resident)
        uint4 pfA[2], pfB[2];
        #pragma unroll
        for (int p = 0; p < 2; ++p) {
            pfA[p] = __ldg(W1h + (0 * 32 + npA + p) * 32 + lane);
            pfB[p] = __ldg(W1h + (1 * 32 + npA + p) * 32 + lane);
        }

        #pragma unroll
        for (int ka = 0; ka < KA16; ka += 2) {
            // ---- even k-atom (pfA) ----
            {
                uint4 av0 = Za[((wm * 2 + 0) * KA16 + ka) * 32 + lane];
                uint4 av1 = Za[((wm * 2 + 1) * KA16 + ka) * 32 + lane];
                u32 a0[4] = {av0.x, av0.y, av0.z, av0.w};
                u32 a1[4] = {av1.x, av1.y, av1.z, av1.w};
                MMAH(d1[0][0], a0, pfA[0].x, pfA[0].y);
                MMAH(d1[1][0], a1, pfA[0].x, pfA[0].y);
                MMAH(d1[0][1], a0, pfA[0].z, pfA[0].w);
                MMAH(d1[1][1], a1, pfA[0].z, pfA[0].w);
                MMAH(d1[0][2], a0, pfA[1].x, pfA[1].y);
                MMAH(d1[1][2], a1, pfA[1].x, pfA[1].y);
                MMAH(d1[0][3], a0, pfA[1].z, pfA[1].w);
                MMAH(d1[1][3], a1, pfA[1].z, pfA[1].w);
                if (ka + 2 < KA16) {
                    #pragma unroll
                    for (int p = 0; p < 2; ++p)
                        pfA[p] = __ldg(W1h + ((ka + 2) * 32 + npA + p) * 32 + lane);
                }
            }
            // ---- odd k-atom (pfB) ----
            {
                uint4 av0 = Za[((wm * 2 + 0) * KA16 + ka + 1) * 32 + lane];
                uint4 av1 = Za[((wm * 2 + 1) * KA16 + ka + 1) * 32 + lane];
                u32 a0[4] = {av0.x, av0.y, av0.z, av0.w};
                u32 a1[4] = {av1.x, av1.y, av1.z, av1.w};
                MMAH(d1[0][0], a0, pfB[0].x, pfB[0].y);
                MMAH(d1[1][0], a1, pfB[0].x, pfB[0].y);
                MMAH(d1[0][1], a0, pfB[0].z, pfB[0].w);
                MMAH(d1[1][1], a1, pfB[0].z, pfB[0].w);
                MMAH(d1[0][2], a0, pfB[1].x, pfB[1].y);
                MMAH(d1[1][2], a1, pfB[1].x, pfB[1].y);
                MMAH(d1[0][3], a0, pfB[1].z, pfB[1].w);
                MMAH(d1[1][3], a1, pfB[1].z, pfB[1].w);
                if (ka + 3 < KA16) {
                    #pragma unroll
                    for (int p = 0; p < 2; ++p)
                        pfB[p] = __ldg(W1h + ((ka + 3) * 32 + npA + p) * 32 + lane);
                }
            }
        }

        // ---- gelu (fp16x2 tanh) + GEMM2 partial, h fed straight from registers ----
        const int colbase = nc * 128 + wn * 32;
        #pragma unroll
        for (int pg = 0; pg < 2; ++pg) {
            int cE = colbase + (2 * pg) * 8 + ccol;       // even atom cols
            int cO = cE + 8;                              // odd atom cols
            float bEa = b1s[cE], bEb = b1s[cE + 1];
            float bOa = b1s[cO], bOb = b1s[cO + 1];
            u32 A2[2][4];
            #pragma unroll
            for (int m = 0; m < 2; ++m) {
                A2[m][0] = gelu2(d1[m][2*pg][0]   + bEa, d1[m][2*pg][1]   + bEb);
                A2[m][1] = gelu2(d1[m][2*pg][2]   + bEa, d1[m][2*pg][3]   + bEb);
                A2[m][2] = gelu2(d1[m][2*pg+1][0] + bOa, d1[m][2*pg+1][1] + bOb);
                A2[m][3] = gelu2(d1[m][2*pg+1][2] + bOa, d1[m][2*pg+1][3] + bOb);
            }
            int gka = nc * 8 + wn * 2 + pg;               // H 16-row block (0..31)
            #pragma unroll
            for (int pa = 0; pa < 2; ++pa) {
                uint4 w = __ldg(W2h + (gka * 2 + pa) * 32 + lane);
                MMAH(d2[0][2*pa],   A2[0], w.x, w.y);
                MMAH(d2[1][2*pa],   A2[1], w.x, w.y);
                MMAH(d2[0][2*pa+1], A2[0], w.z, w.w);
                MMAH(d2[1][2*pa+1], A2[1], w.z, w.w);
            }
        }
    }

    __syncthreads();   // all Zf reads done before red overwrites it

    // ---- cross-wn reduction: wn=1..3 store partial d2, wn=0 adds ----
    if (wn >= 1) {
        float* rp = red + ((wn - 1) * 64 + wm * 32 + lane) * 36;
        #pragma unroll
        for (int m = 0; m < 2; ++m)
            #pragma unroll
            for (int a = 0; a < 4; ++a)
                *(float4*)&rp[(m * 4 + a) * 4] =
                    make_float4(d2[m][a][0], d2[m][a][1], d2[m][a][2], d2[m][a][3]);
    }
    __syncthreads();

    if (wn == 0) {
        #pragma unroll
        for (int s = 0; s < 3; ++s) {
            const float* rp = red + (s * 64 + wm * 32 + lane) * 36;
            #pragma unroll
            for (int m = 0; m < 2; ++m)
                #pragma unroll
                for (int a = 0; a < 4; ++a) {
                    float4 v = *(const float4*)&rp[(m * 4 + a) * 4];
                    d2[m][a][0] += v.x; d2[m][a][1] += v.y;
                    d2[m][a][2] += v.z; d2[m][a][3] += v.w;
                }
        }
        // epilogue: dst[row][c..c+1] = x + 0.1*(d2 + b2)
        #pragma unroll
        for (int m = 0; m < 2; ++m)
            #pragma unroll
            for (int rr = 0; rr < 2; ++rr) {
                int row = wm * 32 + m * 16 + rr * 8 + (lane >> 2);
                if (row < rows_valid) {
                    size_t rb = (size_t)(m0 + row) * Dn;
                    #pragma unroll
                    for (int a = 0; a < 4; ++a) {
                        int c = a * 8 + ccol;
                        float2 xv = __ldg((const float2*)(src + rb + c));
                        float2 ov;
                        ov.x = xv.x + 0.1f * (d2[m][a][rr*2]     + b2s[c]);
                        ov.y = xv.y + 0.1f * (d2[m][a][rr*2 + 1] + b2s[c+1]);
                        *(float2*)(dst + rb + c) = ov;
                    }
                }
            }
    } else if (wn == 1) {
        // static dims 32..39 (unchanged by Euler step); 2 warps cover 64 rows
        int row = wm * 32 + lane;
        if (row < rows_valid) {
            size_t rb = (size_t)(m0 + row) * Dn;
            float4 s0 = __ldg((const float4*)(src + rb + 32));
            float4 s1 = __ldg((const float4*)(src + rb + 36));
            *(float4*)(dst + rb + 32) = s0;
            *(float4*)(dst + rb + 36) = s1;
        }
    }
}

extern "C" void kernel_launch(void* const* d_in, const int* in_sizes, int n_in,
                              void* d_out, int out_size)
{
    const float* x     = (const float*)d_in[0];
    const int*   index = (const int*)  d_in[1];
    const float* W1    = (const float*)d_in[2];
    const float* b1    = (const float*)d_in[3];
    const float* W2    = (const float*)d_in[4];
    const float* b2    = (const float*)d_in[5];
    float* out = (float*)d_out;

    float* buf = nullptr;
    uint4 *w1h = nullptr, *w2h = nullptr;
    cudaGetSymbolAddress((void**)&buf, g_xbuf);
    cudaGetSymbolAddress((void**)&w1h, g_W1h);
    cudaGetSymbolAddress((void**)&w2h, g_W2h);

    cudaFuncSetAttribute(step_kernel, cudaFuncAttributeMaxDynamicSharedMemorySize, SMEM_BYTES);

    prep_w1h<<<(KA16*32*32*4 + 255)/256, 256>>>(W1);
    prep_w2h<<<(32*2*32*4 + 255)/256, 256>>>(W2);

    dim3 grid(NBLK), block(NTH);
    step_kernel<<<grid, block, SMEM_BYTES>>>(x,   buf, index, w1h, w2h, b1, b2);
    step_kernel<<<grid, block, SMEM_BYTES>>>(buf, out, index, w1h, w2h, b1, b2);
    step_kernel<<<grid, block, SMEM_BYTES>>>(out, buf, index, w1h, w2h, b1, b2);
    step_kernel<<<grid, block, SMEM_BYTES>>>(buf, out, index, w1h, w2h, b1, b2);
}

// round 10
// speedup vs baseline: 1.4910x; 1.4910x over previous
#include <cuda_runtime.h>
#include <cuda_fp16.h>
#include <cstdint>

typedef unsigned int u32;

// ---------------- problem constants ----------------
#define Bn 8
#define Nn 40962
#define Dn 40
#define Hn 512
#define DDn 32
#define KTOT 160               // 4 neighbors * 40
#define M_TOT (Bn*Nn)          // 327696
#define TMm 64                 // rows per CTA (2 CTAs/SM)
#define NTH 256
#define NBLK ((M_TOT + TMm - 1)/TMm)   // 5121
#define KA16 10                // GEMM1 k-atoms of 16 (160/16)

// ---------------- smem layout (u32 indices) ----------------
// region A: max(Zf 5120 u32, red 6912 f32) = 6912
#define SM_Z    0
#define SM_B1   6912
#define SM_B2   (SM_B1 + 512)
#define SM_BAS  (SM_B2 + 32)
#define SM_U32S (SM_BAS + 256)         // 7712
#define SMEM_BYTES (SM_U32S*4)         // 30848

// ---------------- helpers ----------------
__device__ __forceinline__ u32 pack2(float a, float b) {
    __half2 h = __floats2half2_rn(a, b);
    return *(u32*)&h;
}
// paired gelu -> packed fp16x2, one MUFU per pair (tanh.approx.f16x2)
__device__ __forceinline__ u32 gelu2(float x0, float x1) {
    float u0 = x0 * (0.7978845608028654f + 0.0356774081f * x0 * x0);
    float u1 = x1 * (0.7978845608028654f + 0.0356774081f * x1 * x1);
    u32 uh = pack2(u0, u1);
    u32 th; asm("tanh.approx.f16x2 %0, %1;" : "=r"(th) : "r"(uh));
    __half2 t = *(__half2*)&th;
    __half2 xh = __floats2half2_rn(x0, x1);
    const __half2 c05 = __float2half2_rn(0.5f);
    __half2 h = __hmul2(xh, __hfma2(t, c05, c05));   // x * (0.5*t + 0.5)
    return *(u32*)&h;
}

// m16n8k16 fp16 HMMA: D(f32) += A(f16) * B(f16)
#define MMAH(D, A, b0, b1) \
    asm("mma.sync.aligned.m16n8k16.row.col.f32.f16.f16.f32 " \
        "{%0,%1,%2,%3}, {%4,%5,%6,%7}, {%8,%9}, {%0,%1,%2,%3};" \
        : "+f"((D)[0]), "+f"((D)[1]), "+f"((D)[2]), "+f"((D)[3]) \
        : "r"((A)[0]), "r"((A)[1]), "r"((A)[2]), "r"((A)[3]), "r"(b0), "r"(b1))

// ---------------- global scratch ----------------
// W1 fp16 B-fragments: [ka16(10)][npair(32)][lane(32)] x uint4
__device__ uint4 g_W1h[KA16 * 32 * 32];
// W2 fp16 B-fragments: [gka16(32)][pa(2)][lane(32)] x uint4
__device__ uint4 g_W2h[32 * 2 * 32];
__device__ float g_xbuf[(size_t)M_TOT * Dn];

// prep: W1 -> fp16 B-frag order.
// (ka, npair, lane, q): k = ka*16 + (lane%4)*2 + {0,1} + (q&1)*8
//                       n = npair*16 + (q>>1)*8 + lane/4
__global__ void prep_w1h(const float* __restrict__ W1) {
    int i = blockIdx.x * 256 + threadIdx.x;
    if (i >= KA16 * 32 * 32 * 4) return;
    int q    = i & 3;
    int lane = (i >> 2) & 31;
    int np   = (i >> 7) & 31;
    int ka   = i >> 12;
    int k = ka * 16 + (lane & 3) * 2 + (q & 1) * 8;
    int n = np * 16 + ((q >> 1) << 3) + (lane >> 2);
    float v0 = __ldg(&W1[(size_t)k * Hn + n]);
    float v1 = __ldg(&W1[(size_t)(k + 1) * Hn + n]);
    ((u32*)g_W1h)[i] = pack2(v0, v1);
}

// prep: W2 -> fp16 B-frag order (identity k mapping).
__global__ void prep_w2h(const float* __restrict__ W2) {
    int i = blockIdx.x * 256 + threadIdx.x;
    if (i >= 32 * 2 * 32 * 4) return;
    int q    = i & 3;
    int lane = (i >> 2) & 31;
    int pa   = (i >> 7) & 1;
    int gka  = i >> 8;
    int r = gka * 16 + (lane & 3) * 2 + (q & 1) * 8;
    int n = pa * 16 + ((q >> 1) << 3) + (lane >> 2);
    float v0 = __ldg(&W2[r * DDn + n]);
    float v1 = __ldg(&W2[(r + 1) * DDn + n]);
    ((u32*)g_W2h)[i] = pack2(v0, v1);
}

// ---------------- fused Euler step ----------------
__global__ void __launch_bounds__(NTH, 2)
step_kernel(const float* __restrict__ src, float* __restrict__ dst,
            const int* __restrict__ index,
            const uint4* __restrict__ W1h, const uint4* __restrict__ W2h,
            const float* __restrict__ b1, const float* __restrict__ b2)
{
    extern __shared__ u32 smu[];
    u32*   Zu  = smu;                    // fp16 A-frags: [mb(4)][ka16(10)][lane(32)][slot(4)]
    float* b1s = (float*)(smu + SM_B1);
    float* b2s = (float*)(smu + SM_B2);
    int*   bas = (int*)(smu + SM_BAS);
    float* red = (float*)smu;            // reduction scratch reuses Zf after GEMMs

    const int tid  = threadIdx.x;
    const int lane = tid & 31;
    const int wid  = tid >> 5;
    const int wm   = wid & 1;    // M warp: rows wm*32
    const int wn   = wid >> 1;   // N warp: 32-col slice within each 128-chunk (0..3)
    const int m0   = blockIdx.x * TMm;
    const int rows_valid = min(TMm, M_TOT - m0);

    // gather bases (one per thread: 64 rows x 4 neighbors)
    {
        int r = tid >> 2, k = tid & 3;
        int base = 0;
        if (r < rows_valid) {
            int m = m0 + r, b = m / Nn, n = m - b * Nn;
            base = (b * Nn + __ldg(&index[n * 4 + k])) * Dn;
        }
        bas[tid] = base;
    }
    if (tid < 128) ((float4*)b1s)[tid] = __ldg(((const float4*)b1) + tid);
    if (tid < 8)   ((float4*)b2s)[tid] = __ldg(((const float4*)b2) + tid);
    __syncthreads();

    // ---- gather Z -> fp16 A-fragment layout ----
    // d4-major mapping (adjacent lanes read adjacent 16B of the same row: ~5 L1
    // wavefronts per LDG.128 instead of 32) + full MLP batching (10 in flight).
    {
        float4 gv[10];
        int rka[10], d4a[10];
        #pragma unroll
        for (int j = 0; j < 10; ++j) {
            int t  = j * NTH + tid;          // 0..2559
            int rk = t / 10;
            int d4 = t - rk * 10;
            rka[j] = rk; d4a[j] = d4;
            gv[j] = __ldg((const float4*)(src + bas[rk] + d4 * 4));
        }
        #pragma unroll
        for (int j = 0; j < 10; ++j) {
            int rk = rka[j], d4 = d4a[j];
            int r  = rk >> 2, kn = rk & 3;
            int K  = kn * 40 + d4 * 4;
            int ka = K >> 4, kk = K & 15;
            int mb = r >> 4, rr = r & 15;
            int lane0 = ((rr & 7) << 2) + ((kk & 7) >> 1);
            int slot  = (rr >> 3) + ((kk >> 3) << 1);
            int base  = ((mb * KA16 + ka) * 32 + lane0) * 4 + slot;
            Zu[base]     = pack2(gv[j].x, gv[j].y);
            Zu[base + 4] = pack2(gv[j].z, gv[j].w);
        }
    }
    __syncthreads();

    float d2[2][4][4];
    #pragma unroll
    for (int m = 0; m < 2; ++m)
        #pragma unroll
        for (int a = 0; a < 4; ++a)
            #pragma unroll
            for (int q = 0; q < 4; ++q) d2[m][a][q] = 0.f;

    const uint4* Za = (const uint4*)Zu;
    const int np0  = wn * 2;     // warp's first npair within each 128-col chunk
    const int ccol = 2 * (lane & 3);

    // ---- 4 H-chunks of 128 cols; NOT unrolled (unroll=1): full unroll spills
    //      past the 128-reg cap and pushes d1/pf to local memory (R9 regression) ----
    #pragma unroll 1
    for (int nc = 0; nc < 4; ++nc) {
        const int npA = nc * 8 + np0;     // warp's npair indices: npA, npA+1
        float d1[2][4][4];
        #pragma unroll
        for (int m = 0; m < 2; ++m)
            #pragma unroll
            for (int a = 0; a < 4; ++a)
                #pragma unroll
                for (int q = 0; q < 4; ++q) d1[m][a][q] = 0.f;

        // distance-2 register prefetch of W1 fp16 B-frags (L2-resident)
        uint4 pfA[2], pfB[2];
        #pragma unroll
        for (int p = 0; p < 2; ++p) {
            pfA[p] = __ldg(W1h + (0 * 32 + npA + p) * 32 + lane);
            pfB[p] = __ldg(W1h + (1 * 32 + npA + p) * 32 + lane);
        }

        #pragma unroll
        for (int ka = 0; ka < KA16; ka += 2) {
            // ---- even k-atom (pfA) ----
            {
                uint4 av0 = Za[((wm * 2 + 0) * KA16 + ka) * 32 + lane];
                uint4 av1 = Za[((wm * 2 + 1) * KA16 + ka) * 32 + lane];
                u32 a0[4] = {av0.x, av0.y, av0.z, av0.w};
                u32 a1[4] = {av1.x, av1.y, av1.z, av1.w};
                MMAH(d1[0][0], a0, pfA[0].x, pfA[0].y);
                MMAH(d1[1][0], a1, pfA[0].x, pfA[0].y);
                MMAH(d1[0][1], a0, pfA[0].z, pfA[0].w);
                MMAH(d1[1][1], a1, pfA[0].z, pfA[0].w);
                MMAH(d1[0][2], a0, pfA[1].x, pfA[1].y);
                MMAH(d1[1][2], a1, pfA[1].x, pfA[1].y);
                MMAH(d1[0][3], a0, pfA[1].z, pfA[1].w);
                MMAH(d1[1][3], a1, pfA[1].z, pfA[1].w);
                if (ka + 2 < KA16) {
                    #pragma unroll
                    for (int p = 0; p < 2; ++p)
                        pfA[p] = __ldg(W1h + ((ka + 2) * 32 + npA + p) * 32 + lane);
                }
            }
            // ---- odd k-atom (pfB) ----
            {
                uint4 av0 = Za[((wm * 2 + 0) * KA16 + ka + 1) * 32 + lane];
                uint4 av1 = Za[((wm * 2 + 1) * KA16 + ka + 1) * 32 + lane];
                u32 a0[4] = {av0.x, av0.y, av0.z, av0.w};
                u32 a1[4] = {av1.x, av1.y, av1.z, av1.w};
                MMAH(d1[0][0], a0, pfB[0].x, pfB[0].y);
                MMAH(d1[1][0], a1, pfB[0].x, pfB[0].y);
                MMAH(d1[0][1], a0, pfB[0].z, pfB[0].w);
                MMAH(d1[1][1], a1, pfB[0].z, pfB[0].w);
                MMAH(d1[0][2], a0, pfB[1].x, pfB[1].y);
                MMAH(d1[1][2], a1, pfB[1].x, pfB[1].y);
                MMAH(d1[0][3], a0, pfB[1].z, pfB[1].w);
                MMAH(d1[1][3], a1, pfB[1].z, pfB[1].w);
                if (ka + 3 < KA16) {
                    #pragma unroll
                    for (int p = 0; p < 2; ++p)
                        pfB[p] = __ldg(W1h + ((ka + 3) * 32 + npA + p) * 32 + lane);
                }
            }
        }

        // ---- gelu (fp16x2 tanh) + GEMM2 partial, h fed straight from registers ----
        const int colbase = nc * 128 + wn * 32;
        #pragma unroll
        for (int pg = 0; pg < 2; ++pg) {
            int cE = colbase + (2 * pg) * 8 + ccol;       // even atom cols
            int cO = cE + 8;                              // odd atom cols
            float bEa = b1s[cE], bEb = b1s[cE + 1];
            float bOa = b1s[cO], bOb = b1s[cO + 1];
            u32 A2[2][4];
            #pragma unroll
            for (int m = 0; m < 2; ++m) {
                A2[m][0] = gelu2(d1[m][2*pg][0]   + bEa, d1[m][2*pg][1]   + bEb);
                A2[m][1] = gelu2(d1[m][2*pg][2]   + bEa, d1[m][2*pg][3]   + bEb);
                A2[m][2] = gelu2(d1[m][2*pg+1][0] + bOa, d1[m][2*pg+1][1] + bOb);
                A2[m][3] = gelu2(d1[m][2*pg+1][2] + bOa, d1[m][2*pg+1][3] + bOb);
            }
            int gka = nc * 8 + wn * 2 + pg;               // H 16-row block (0..31)
            #pragma unroll
            for (int pa = 0; pa < 2; ++pa) {
                uint4 w = __ldg(W2h + (gka * 2 + pa) * 32 + lane);
                MMAH(d2[0][2*pa],   A2[0], w.x, w.y);
                MMAH(d2[1][2*pa],   A2[1], w.x, w.y);
                MMAH(d2[0][2*pa+1], A2[0], w.z, w.w);
                MMAH(d2[1][2*pa+1], A2[1], w.z, w.w);
            }
        }
    }

    __syncthreads();   // all Zf reads done before red overwrites it

    // ---- cross-wn reduction: wn=1..3 store partial d2, wn=0 adds ----
    if (wn >= 1) {
        float* rp = red + ((wn - 1) * 64 + wm * 32 + lane) * 36;
        #pragma unroll
        for (int m = 0; m < 2; ++m)
            #pragma unroll
            for (int a = 0; a < 4; ++a)
                *(float4*)&rp[(m * 4 + a) * 4] =
                    make_float4(d2[m][a][0], d2[m][a][1], d2[m][a][2], d2[m][a][3]);
    }
    __syncthreads();

    if (wn == 0) {
        #pragma unroll
        for (int s = 0; s < 3; ++s) {
            const float* rp = red + (s * 64 + wm * 32 + lane) * 36;
            #pragma unroll
            for (int m = 0; m < 2; ++m)
                #pragma unroll
                for (int a = 0; a < 4; ++a) {
                    float4 v = *(const float4*)&rp[(m * 4 + a) * 4];
                    d2[m][a][0] += v.x; d2[m][a][1] += v.y;
                    d2[m][a][2] += v.z; d2[m][a][3] += v.w;
                }
        }
        // epilogue: dst[row][c..c+1] = x + 0.1*(d2 + b2)
        #pragma unroll
        for (int m = 0; m < 2; ++m)
            #pragma unroll
            for (int rr = 0; rr < 2; ++rr) {
                int row = wm * 32 + m * 16 + rr * 8 + (lane >> 2);
                if (row < rows_valid) {
                    size_t rb = (size_t)(m0 + row) * Dn;
                    #pragma unroll
                    for (int a = 0; a < 4; ++a) {
                        int c = a * 8 + ccol;
                        float2 xv = __ldg((const float2*)(src + rb + c));
                        float2 ov;
                        ov.x = xv.x + 0.1f * (d2[m][a][rr*2]     + b2s[c]);
                        ov.y = xv.y + 0.1f * (d2[m][a][rr*2 + 1] + b2s[c+1]);
                        *(float2*)(dst + rb + c) = ov;
                    }
                }
            }
    } else if (wn == 1) {
        // static dims 32..39 (unchanged by Euler step); 2 warps cover 64 rows
        int row = wm * 32 + lane;
        if (row < rows_valid) {
            size_t rb = (size_t)(m0 + row) * Dn;
            float4 s0 = __ldg((const float4*)(src + rb + 32));
            float4 s1 = __ldg((const float4*)(src + rb + 36));
            *(float4*)(dst + rb + 32) = s0;
            *(float4*)(dst + rb + 36) = s1;
        }
    }
}

extern "C" void kernel_launch(void* const* d_in, const int* in_sizes, int n_in,
                              void* d_out, int out_size)
{
    const float* x     = (const float*)d_in[0];
    const int*   index = (const int*)  d_in[1];
    const float* W1    = (const float*)d_in[2];
    const float* b1    = (const float*)d_in[3];
    const float* W2    = (const float*)d_in[4];
    const float* b2    = (const float*)d_in[5];
    float* out = (float*)d_out;

    float* buf = nullptr;
    uint4 *w1h = nullptr, *w2h = nullptr;
    cudaGetSymbolAddress((void**)&buf, g_xbuf);
    cudaGetSymbolAddress((void**)&w1h, g_W1h);
    cudaGetSymbolAddress((void**)&w2h, g_W2h);

    cudaFuncSetAttribute(step_kernel, cudaFuncAttributeMaxDynamicSharedMemorySize, SMEM_BYTES);

    prep_w1h<<<(KA16*32*32*4 + 255)/256, 256>>>(W1);
    prep_w2h<<<(32*2*32*4 + 255)/256, 256>>>(W2);

    dim3 grid(NBLK), block(NTH);
    step_kernel<<<grid, block, SMEM_BYTES>>>(x,   buf, index, w1h, w2h, b1, b2);
    step_kernel<<<grid, block, SMEM_BYTES>>>(buf, out, index, w1h, w2h, b1, b2);
    step_kernel<<<grid, block, SMEM_BYTES>>>(out, buf, index, w1h, w2h, b1, b2);
    step_kernel<<<grid, block, SMEM_BYTES>>>(buf, out, index, w1h, w2h, b1, b2);
}

// round 11
// speedup vs baseline: 1.6098x; 1.0797x over previous
#include <cuda_runtime.h>
#include <cuda_fp16.h>
#include <cstdint>

typedef unsigned int u32;

// ---------------- problem constants ----------------
#define Bn 8
#define Nn 40962
#define Dn 40
#define Hn 512
#define DDn 32
#define KTOT 160               // 4 neighbors * 40
#define M_TOT (Bn*Nn)          // 327696
#define TMm 32                 // rows per CTA (4 CTAs/SM)
#define NTH 128
#define NBLK ((M_TOT + TMm - 1)/TMm)   // 10241
#define KA16 10                // GEMM1 k-atoms of 16 (160/16)

// ---------------- smem layout (u32 indices) ----------------
// region A: max(Zf 2560 u32, red 3456 f32) = 3456
#define SM_Z    0
#define SM_B1   3456
#define SM_B2   (SM_B1 + 512)
#define SM_BAS  (SM_B2 + 32)
#define SM_U32S (SM_BAS + 128)         // 4128
#define SMEM_BYTES (SM_U32S*4)         // 16512

// ---------------- helpers ----------------
__device__ __forceinline__ u32 pack2(float a, float b) {
    __half2 h = __floats2half2_rn(a, b);
    return *(u32*)&h;
}
// paired gelu -> packed fp16x2, one MUFU per pair (tanh.approx.f16x2)
__device__ __forceinline__ u32 gelu2(float x0, float x1) {
    float u0 = x0 * (0.7978845608028654f + 0.0356774081f * x0 * x0);
    float u1 = x1 * (0.7978845608028654f + 0.0356774081f * x1 * x1);
    u32 uh = pack2(u0, u1);
    u32 th; asm("tanh.approx.f16x2 %0, %1;" : "=r"(th) : "r"(uh));
    __half2 t = *(__half2*)&th;
    __half2 xh = __floats2half2_rn(x0, x1);
    const __half2 c05 = __float2half2_rn(0.5f);
    __half2 h = __hmul2(xh, __hfma2(t, c05, c05));   // x * (0.5*t + 0.5)
    return *(u32*)&h;
}

// m16n8k16 fp16 HMMA: D(f32) += A(f16) * B(f16)
#define MMAH(D, A, b0, b1) \
    asm("mma.sync.aligned.m16n8k16.row.col.f32.f16.f16.f32 " \
        "{%0,%1,%2,%3}, {%4,%5,%6,%7}, {%8,%9}, {%0,%1,%2,%3};" \
        : "+f"((D)[0]), "+f"((D)[1]), "+f"((D)[2]), "+f"((D)[3]) \
        : "r"((A)[0]), "r"((A)[1]), "r"((A)[2]), "r"((A)[3]), "r"(b0), "r"(b1))

// ---------------- global scratch ----------------
// W1 fp16 B-fragments: [ka16(10)][npair(32)][lane(32)] x uint4
__device__ uint4 g_W1h[KA16 * 32 * 32];
// W2 fp16 B-fragments: [gka16(32)][pa(2)][lane(32)] x uint4
__device__ uint4 g_W2h[32 * 2 * 32];
__device__ float g_xbuf[(size_t)M_TOT * Dn];

// prep: W1 -> fp16 B-frag order.
// (ka, npair, lane, q): k = ka*16 + (lane%4)*2 + {0,1} + (q&1)*8
//                       n = npair*16 + (q>>1)*8 + lane/4
__global__ void prep_w1h(const float* __restrict__ W1) {
    int i = blockIdx.x * 256 + threadIdx.x;
    if (i >= KA16 * 32 * 32 * 4) return;
    int q    = i & 3;
    int lane = (i >> 2) & 31;
    int np   = (i >> 7) & 31;
    int ka   = i >> 12;
    int k = ka * 16 + (lane & 3) * 2 + (q & 1) * 8;
    int n = np * 16 + ((q >> 1) << 3) + (lane >> 2);
    float v0 = __ldg(&W1[(size_t)k * Hn + n]);
    float v1 = __ldg(&W1[(size_t)(k + 1) * Hn + n]);
    ((u32*)g_W1h)[i] = pack2(v0, v1);
}

// prep: W2 -> fp16 B-frag order (identity k mapping).
__global__ void prep_w2h(const float* __restrict__ W2) {
    int i = blockIdx.x * 256 + threadIdx.x;
    if (i >= 32 * 2 * 32 * 4) return;
    int q    = i & 3;
    int lane = (i >> 2) & 31;
    int pa   = (i >> 7) & 1;
    int gka  = i >> 8;
    int r = gka * 16 + (lane & 3) * 2 + (q & 1) * 8;
    int n = pa * 16 + ((q >> 1) << 3) + (lane >> 2);
    float v0 = __ldg(&W2[r * DDn + n]);
    float v1 = __ldg(&W2[(r + 1) * DDn + n]);
    ((u32*)g_W2h)[i] = pack2(v0, v1);
}

// ---------------- fused Euler step ----------------
__global__ void __launch_bounds__(NTH, 4)
step_kernel(const float* __restrict__ src, float* __restrict__ dst,
            const int* __restrict__ index,
            const uint4* __restrict__ W1h, const uint4* __restrict__ W2h,
            const float* __restrict__ b1, const float* __restrict__ b2)
{
    extern __shared__ u32 smu[];
    u32*   Zu  = smu;                    // fp16 A-frags: [mb(2)][ka16(10)][lane(32)][slot(4)]
    float* b1s = (float*)(smu + SM_B1);
    float* b2s = (float*)(smu + SM_B2);
    int*   bas = (int*)(smu + SM_BAS);
    float* red = (float*)smu;            // reduction scratch reuses Zf after GEMMs

    const int tid  = threadIdx.x;
    const int lane = tid & 31;
    const int wn   = tid >> 5;   // warp = N slice: 32-col slice within each 128-chunk (0..3)
    const int m0   = blockIdx.x * TMm;
    const int rows_valid = min(TMm, M_TOT - m0);

    // gather bases (one per thread: 32 rows x 4 neighbors)
    {
        int r = tid >> 2, k = tid & 3;
        int base = 0;
        if (r < rows_valid) {
            int m = m0 + r, b = m / Nn, n = m - b * Nn;
            base = (b * Nn + __ldg(&index[n * 4 + k])) * Dn;
        }
        bas[tid] = base;
    }
    ((float4*)b1s)[tid] = __ldg(((const float4*)b1) + tid);     // 128 float4 = 512 floats
    if (tid < 8) ((float4*)b2s)[tid] = __ldg(((const float4*)b2) + tid);
    __syncthreads();

    // ---- gather Z -> fp16 A-fragment layout ----
    // d4-major mapping (adjacent lanes read adjacent 16B of the same row) + full
    // MLP batching (10 LDG.128 in flight per thread).
    {
        float4 gv[10];
        int rka[10], d4a[10];
        #pragma unroll
        for (int j = 0; j < 10; ++j) {
            int t  = j * NTH + tid;          // 0..1279
            int rk = t / 10;
            int d4 = t - rk * 10;
            rka[j] = rk; d4a[j] = d4;
            gv[j] = __ldg((const float4*)(src + bas[rk] + d4 * 4));
        }
        #pragma unroll
        for (int j = 0; j < 10; ++j) {
            int rk = rka[j], d4 = d4a[j];
            int r  = rk >> 2, kn = rk & 3;
            int K  = kn * 40 + d4 * 4;
            int ka = K >> 4, kk = K & 15;
            int mb = r >> 4, rr = r & 15;
            int lane0 = ((rr & 7) << 2) + ((kk & 7) >> 1);
            int slot  = (rr >> 3) + ((kk >> 3) << 1);
            int base  = ((mb * KA16 + ka) * 32 + lane0) * 4 + slot;
            Zu[base]     = pack2(gv[j].x, gv[j].y);
            Zu[base + 4] = pack2(gv[j].z, gv[j].w);
        }
    }
    __syncthreads();

    float d2[2][4][4];
    #pragma unroll
    for (int m = 0; m < 2; ++m)
        #pragma unroll
        for (int a = 0; a < 4; ++a)
            #pragma unroll
            for (int q = 0; q < 4; ++q) d2[m][a][q] = 0.f;

    const uint4* Za = (const uint4*)Zu;
    const int np0  = wn * 2;     // warp's first npair within each 128-col chunk
    const int ccol = 2 * (lane & 3);

    // ---- 4 H-chunks of 128 cols; NOT unrolled (R9: full unroll spills) ----
    #pragma unroll 1
    for (int nc = 0; nc < 4; ++nc) {
        const int npA = nc * 8 + np0;     // warp's npair indices: npA, npA+1
        float d1[2][4][4];
        #pragma unroll
        for (int m = 0; m < 2; ++m)
            #pragma unroll
            for (int a = 0; a < 4; ++a)
                #pragma unroll
                for (int q = 0; q < 4; ++q) d1[m][a][q] = 0.f;

        // distance-2 register prefetch of W1 fp16 B-frags (L2/L1-resident)
        uint4 pfA[2], pfB[2];
        #pragma unroll
        for (int p = 0; p < 2; ++p) {
            pfA[p] = __ldg(W1h + (0 * 32 + npA + p) * 32 + lane);
            pfB[p] = __ldg(W1h + (1 * 32 + npA + p) * 32 + lane);
        }

        #pragma unroll
        for (int ka = 0; ka < KA16; ka += 2) {
            // ---- even k-atom (pfA) ----
            {
                uint4 av0 = Za[(0 * KA16 + ka) * 32 + lane];
                uint4 av1 = Za[(1 * KA16 + ka) * 32 + lane];
                u32 a0[4] = {av0.x, av0.y, av0.z, av0.w};
                u32 a1[4] = {av1.x, av1.y, av1.z, av1.w};
                MMAH(d1[0][0], a0, pfA[0].x, pfA[0].y);
                MMAH(d1[1][0], a1, pfA[0].x, pfA[0].y);
                MMAH(d1[0][1], a0, pfA[0].z, pfA[0].w);
                MMAH(d1[1][1], a1, pfA[0].z, pfA[0].w);
                MMAH(d1[0][2], a0, pfA[1].x, pfA[1].y);
                MMAH(d1[1][2], a1, pfA[1].x, pfA[1].y);
                MMAH(d1[0][3], a0, pfA[1].z, pfA[1].w);
                MMAH(d1[1][3], a1, pfA[1].z, pfA[1].w);
                if (ka + 2 < KA16) {
                    #pragma unroll
                    for (int p = 0; p < 2; ++p)
                        pfA[p] = __ldg(W1h + ((ka + 2) * 32 + npA + p) * 32 + lane);
                }
            }
            // ---- odd k-atom (pfB) ----
            {
                uint4 av0 = Za[(0 * KA16 + ka + 1) * 32 + lane];
                uint4 av1 = Za[(1 * KA16 + ka + 1) * 32 + lane];
                u32 a0[4] = {av0.x, av0.y, av0.z, av0.w};
                u32 a1[4] = {av1.x, av1.y, av1.z, av1.w};
                MMAH(d1[0][0], a0, pfB[0].x, pfB[0].y);
                MMAH(d1[1][0], a1, pfB[0].x, pfB[0].y);
                MMAH(d1[0][1], a0, pfB[0].z, pfB[0].w);
                MMAH(d1[1][1], a1, pfB[0].z, pfB[0].w);
                MMAH(d1[0][2], a0, pfB[1].x, pfB[1].y);
                MMAH(d1[1][2], a1, pfB[1].x, pfB[1].y);
                MMAH(d1[0][3], a0, pfB[1].z, pfB[1].w);
                MMAH(d1[1][3], a1, pfB[1].z, pfB[1].w);
                if (ka + 3 < KA16) {
                    #pragma unroll
                    for (int p = 0; p < 2; ++p)
                        pfB[p] = __ldg(W1h + ((ka + 3) * 32 + npA + p) * 32 + lane);
                }
            }
        }

        // ---- gelu (fp16x2 tanh) + GEMM2 partial, h fed straight from registers ----
        const int colbase = nc * 128 + wn * 32;
        #pragma unroll
        for (int pg = 0; pg < 2; ++pg) {
            int cE = colbase + (2 * pg) * 8 + ccol;       // even atom cols
            int cO = cE + 8;                              // odd atom cols
            float bEa = b1s[cE], bEb = b1s[cE + 1];
            float bOa = b1s[cO], bOb = b1s[cO + 1];
            u32 A2[2][4];
            #pragma unroll
            for (int m = 0; m < 2; ++m) {
                A2[m][0] = gelu2(d1[m][2*pg][0]   + bEa, d1[m][2*pg][1]   + bEb);
                A2[m][1] = gelu2(d1[m][2*pg][2]   + bEa, d1[m][2*pg][3]   + bEb);
                A2[m][2] = gelu2(d1[m][2*pg+1][0] + bOa, d1[m][2*pg+1][1] + bOb);
                A2[m][3] = gelu2(d1[m][2*pg+1][2] + bOa, d1[m][2*pg+1][3] + bOb);
            }
            int gka = nc * 8 + wn * 2 + pg;               // H 16-row block (0..31)
            #pragma unroll
            for (int pa = 0; pa < 2; ++pa) {
                uint4 w = __ldg(W2h + (gka * 2 + pa) * 32 + lane);
                MMAH(d2[0][2*pa],   A2[0], w.x, w.y);
                MMAH(d2[1][2*pa],   A2[1], w.x, w.y);
                MMAH(d2[0][2*pa+1], A2[0], w.z, w.w);
                MMAH(d2[1][2*pa+1], A2[1], w.z, w.w);
            }
        }
    }

    __syncthreads();   // all Zf reads done before red overwrites it

    // ---- cross-wn reduction: wn=1..3 store partial d2, wn=0 adds ----
    if (wn >= 1) {
        float* rp = red + ((wn - 1) * 32 + lane) * 36;
        #pragma unroll
        for (int m = 0; m < 2; ++m)
            #pragma unroll
            for (int a = 0; a < 4; ++a)
                *(float4*)&rp[(m * 4 + a) * 4] =
                    make_float4(d2[m][a][0], d2[m][a][1], d2[m][a][2], d2[m][a][3]);
    }
    __syncthreads();

    if (wn == 0) {
        #pragma unroll
        for (int s = 0; s < 3; ++s) {
            const float* rp = red + (s * 32 + lane) * 36;
            #pragma unroll
            for (int m = 0; m < 2; ++m)
                #pragma unroll
                for (int a = 0; a < 4; ++a) {
                    float4 v = *(const float4*)&rp[(m * 4 + a) * 4];
                    d2[m][a][0] += v.x; d2[m][a][1] += v.y;
                    d2[m][a][2] += v.z; d2[m][a][3] += v.w;
                }
        }
        // epilogue: dst[row][c..c+1] = x + 0.1*(d2 + b2)
        #pragma unroll
        for (int m = 0; m < 2; ++m)
            #pragma unroll
            for (int rr = 0; rr < 2; ++rr) {
                int row = m * 16 + rr * 8 + (lane >> 2);
                if (row < rows_valid) {
                    size_t rb = (size_t)(m0 + row) * Dn;
                    #pragma unroll
                    for (int a = 0; a < 4; ++a) {
                        int c = a * 8 + ccol;
                        float2 xv = __ldg((const float2*)(src + rb + c));
                        float2 ov;
                        ov.x = xv.x + 0.1f * (d2[m][a][rr*2]     + b2s[c]);
                        ov.y = xv.y + 0.1f * (d2[m][a][rr*2 + 1] + b2s[c+1]);
                        *(float2*)(dst + rb + c) = ov;
                    }
                }
            }
    } else if (wn == 1) {
        // static dims 32..39 (unchanged by Euler step); 1 warp covers 32 rows
        int row = lane;
        if (row < rows_valid) {
            size_t rb = (size_t)(m0 + row) * Dn;
            float4 s0 = __ldg((const float4*)(src + rb + 32));
            float4 s1 = __ldg((const float4*)(src + rb + 36));
            *(float4*)(dst + rb + 32) = s0;
            *(float4*)(dst + rb + 36) = s1;
        }
    }
}

extern "C" void kernel_launch(void* const* d_in, const int* in_sizes, int n_in,
                              void* d_out, int out_size)
{
    const float* x     = (const float*)d_in[0];
    const int*   index = (const int*)  d_in[1];
    const float* W1    = (const float*)d_in[2];
    const float* b1    = (const float*)d_in[3];
    const float* W2    = (const float*)d_in[4];
    const float* b2    = (const float*)d_in[5];
    float* out = (float*)d_out;

    float* buf = nullptr;
    uint4 *w1h = nullptr, *w2h = nullptr;
    cudaGetSymbolAddress((void**)&buf, g_xbuf);
    cudaGetSymbolAddress((void**)&w1h, g_W1h);
    cudaGetSymbolAddress((void**)&w2h, g_W2h);

    cudaFuncSetAttribute(step_kernel, cudaFuncAttributeMaxDynamicSharedMemorySize, SMEM_BYTES);

    prep_w1h<<<(KA16*32*32*4 + 255)/256, 256>>>(W1);
    prep_w2h<<<(32*2*32*4 + 255)/256, 256>>>(W2);

    dim3 grid(NBLK), block(NTH);
    step_kernel<<<grid, block, SMEM_BYTES>>>(x,   buf, index, w1h, w2h, b1, b2);
    step_kernel<<<grid, block, SMEM_BYTES>>>(buf, out, index, w1h, w2h, b1, b2);
    step_kernel<<<grid, block, SMEM_BYTES>>>(out, buf, index, w1h, w2h, b1, b2);
    step_kernel<<<grid, block, SMEM_BYTES>>>(buf, out, index, w1h, w2h, b1, b2);
}